// round 15
// baseline (speedup 1.0000x reference)
#include <cuda_runtime.h>
#include <cuda_bf16.h>
#include <cuda_fp16.h>
#include <cstdint>

#define MAXN 4096
#define MAXD 512

__device__ __align__(16) float g_Kbar[MAXD * MAXD];
__device__ __align__(16) float g_M[MAXD * MAXD];
__device__ __align__(16) float g_Mpart[4 * MAXD * MAXD];
__device__ __align__(16) float g_c[MAXD];
__device__ __align__(16) float g_cpart[8 * MAXD];
__device__ __align__(16) float g_P[MAXN * MAXD];
__device__ float g_deg[MAXN];

// ---------------------------------------------------------------------------
// helpers  [R13 verbatim]
// ---------------------------------------------------------------------------
__device__ __forceinline__ void mma16bf(float* d, const uint32_t* a, const uint32_t* b) {
    asm volatile(
        "mma.sync.aligned.m16n8k16.row.col.f32.bf16.bf16.f32 "
        "{%0,%1,%2,%3},{%4,%5,%6,%7},{%8,%9},{%0,%1,%2,%3};\n"
        : "+f"(d[0]), "+f"(d[1]), "+f"(d[2]), "+f"(d[3])
        : "r"(a[0]), "r"(a[1]), "r"(a[2]), "r"(a[3]), "r"(b[0]), "r"(b[1]));
}

__device__ __forceinline__ void mma16h(float* d, const uint32_t* a, const uint32_t* b) {
    asm volatile(
        "mma.sync.aligned.m16n8k16.row.col.f32.f16.f16.f32 "
        "{%0,%1,%2,%3},{%4,%5,%6,%7},{%8,%9},{%0,%1,%2,%3};\n"
        : "+f"(d[0]), "+f"(d[1]), "+f"(d[2]), "+f"(d[3])
        : "r"(a[0]), "r"(a[1]), "r"(a[2]), "r"(a[3]), "r"(b[0]), "r"(b[1]));
}

__device__ __forceinline__ void split_pack_bf(float x0, float x1,
                                              uint32_t& h, uint32_t& l) {
    __nv_bfloat16 h0 = __float2bfloat16(x0), h1 = __float2bfloat16(x1);
    float r0 = x0 - __bfloat162float(h0);
    float r1 = x1 - __bfloat162float(h1);
    __nv_bfloat16 l0 = __float2bfloat16(r0), l1 = __float2bfloat16(r1);
    __nv_bfloat162 hp; hp.x = h0; hp.y = h1;
    __nv_bfloat162 lp; lp.x = l0; lp.y = l1;
    h = *(uint32_t*)&hp;
    l = *(uint32_t*)&lp;
}

__device__ __forceinline__ void split_pack_h(float x0, float x1,
                                             uint32_t& h, uint32_t& l) {
    __half h0 = __float2half_rn(x0), h1 = __float2half_rn(x1);
    float r0 = x0 - __half2float(h0);
    float r1 = x1 - __half2float(h1);
    __half2 hp = __halves2half2(h0, h1);
    __half2 lp = __halves2half2(__float2half_rn(r0), __float2half_rn(r1));
    h = *(uint32_t*)&hp;
    l = *(uint32_t*)&lp;
}

__device__ __forceinline__ uint32_t pack_h2(float x0, float x1) {
    __half2 p = __floats2half2_rn(x0, x1);
    return *(uint32_t*)&p;
}

// ---------------------------------------------------------------------------
// Kbar = mean over heads  [R13 verbatim]
// ---------------------------------------------------------------------------
__global__ void kbar_kernel(const float* __restrict__ K, int H, int DD4) {
    int i = blockIdx.x * blockDim.x + threadIdx.x;
    if (i < DD4) {
        const float4* K4 = (const float4*)K;
        float4 s = make_float4(0, 0, 0, 0);
        for (int h = 0; h < H; h++) {
            float4 x = K4[(size_t)h * DD4 + i];
            s.x += x.x; s.y += x.y; s.z += x.z; s.w += x.w;
        }
        float inv = 1.0f / (float)H;
        ((float4*)g_Kbar)[i] = make_float4(s.x * inv, s.y * inv, s.z * inv, s.w * inv);
    }
}

// ---------------------------------------------------------------------------
// cvec partials from g_Kbar  [R13 verbatim]
// ---------------------------------------------------------------------------
__global__ void cvec_part(const float* __restrict__ b, int D) {
    const int p = blockIdx.x;
    const int tid = threadIdx.x;
    const int dlo = p * (D / 8), dhi = dlo + D / 8;
    float a0 = 0.f, a1 = 0.f;
    for (int d = dlo; d < dhi; d++) {
        float bd = b[d];
        a0 += bd * g_Kbar[(size_t)d * D + tid];
        a1 += bd * g_Kbar[(size_t)d * D + tid + 256];
    }
    g_cpart[p * D + tid] = a0;
    g_cpart[p * D + tid + 256] = a1;
}

// ---------------------------------------------------------------------------
// fused reduce  [R13 verbatim]
// ---------------------------------------------------------------------------
__global__ void reduce_kernel(int DD4, int D) {
    const int nb = DD4 / 256;
    if ((int)blockIdx.x < nb) {
        int i = blockIdx.x * 256 + threadIdx.x;
        const float4* P4 = (const float4*)g_Mpart;
        float4 s = P4[i];
#pragma unroll
        for (int z = 1; z < 4; z++) {
            float4 x = P4[(size_t)z * DD4 + i];
            s.x += x.x; s.y += x.y; s.z += x.z; s.w += x.w;
        }
        ((float4*)g_M)[i] = s;
    } else {
        int f0 = threadIdx.x * 2;
#pragma unroll
        for (int q = 0; q < 2; q++) {
            int f = f0 + q;
            float s = 0.f;
            for (int p = 0; p < 8; p++) s += g_cpart[p * D + f];
            g_c[f] = s;
        }
    }
}

// ---------------------------------------------------------------------------
// Sparse aggregation, 2 rows per block  [R13 verbatim + rowBase offset]
// ---------------------------------------------------------------------------
__global__ void agg2_kernel(const float* __restrict__ adj,
                            const float* __restrict__ nodes,
                            int n, int d, int rowBase) {
    __shared__ int s_idx[2][4096];
    __shared__ int s_cnt[8];
    const int tid  = threadIdx.x;
    const int w    = tid >> 5;
    const int lane = tid & 31;
    const unsigned mlt = (1u << lane) - 1u;

    const int rsel = w >> 2;
    const int wseg = w & 3;
    const int row  = rowBase + blockIdx.x * 2 + rsel;
    const int segN = n >> 2;
    const int base = wseg * segN;
    const float* arow = adj + (size_t)row * n;

    int cnt = 0;
    for (int s = 0; s < segN; s += 128) {
        int c0 = base + s + lane * 4;
        float4 v = *(const float4*)(arow + c0);
        unsigned m;
        m = __ballot_sync(0xffffffffu, v.x > 0.5f);
        if (v.x > 0.5f) s_idx[rsel][base + cnt + __popc(m & mlt)] = c0;
        cnt += __popc(m);
        m = __ballot_sync(0xffffffffu, v.y > 0.5f);
        if (v.y > 0.5f) s_idx[rsel][base + cnt + __popc(m & mlt)] = c0 + 1;
        cnt += __popc(m);
        m = __ballot_sync(0xffffffffu, v.z > 0.5f);
        if (v.z > 0.5f) s_idx[rsel][base + cnt + __popc(m & mlt)] = c0 + 2;
        cnt += __popc(m);
        m = __ballot_sync(0xffffffffu, v.w > 0.5f);
        if (v.w > 0.5f) s_idx[rsel][base + cnt + __popc(m & mlt)] = c0 + 3;
        cnt += __popc(m);
    }
    if (lane == 0) s_cnt[w] = cnt;
    __syncthreads();

    if (tid < 2) {
        int dg = 0;
#pragma unroll
        for (int i = 0; i < 4; i++) dg += s_cnt[tid * 4 + i];
        g_deg[rowBase + blockIdx.x * 2 + tid] = (float)dg;
    }

    const int gr   = tid >> 7;
    const int gl   = tid & 127;
    const int grow = rowBase + blockIdx.x * 2 + gr;
    const int d4 = d >> 2;
    const float4* nodes4 = (const float4*)nodes;
    float4* P4 = (float4*)g_P;

    for (int col = gl; col < d4; col += 128) {
        float4 acc = make_float4(0.f, 0.f, 0.f, 0.f);
        for (int ww = 0; ww < 4; ww++) {
            const int  c   = s_cnt[gr * 4 + ww];
            const int* lst = s_idx[gr] + ww * segN;
            for (int k = 0; k < c; k++) {
                int j = lst[k];
                float4 t = nodes4[(size_t)j * d4 + col];
                acc.x += t.x; acc.y += t.y; acc.z += t.z; acc.w += t.w;
            }
        }
        P4[(size_t)grow * d4 + col] = acc;
    }
}

// ---------------------------------------------------------------------------
// bf16-split 3-product GEMM  [R13 verbatim — M = W @ Kbar]
// ---------------------------------------------------------------------------
template <int BM, int BN, int WGM, int WGN>
__global__ __launch_bounds__(256, 1)
void gemm_bf16(const float* __restrict__ A, const float* __restrict__ B,
               float* __restrict__ C, int Mdim, int Ndim, int Kfull) {
    constexpr int WM = BM / WGM, WN = BN / WGN;
    constexpr int MT = WM / 16, NT = WN / 8;
    constexpr int SA = BM + 8, SB = BN + 8;
    constexpr int LA = BM / 64;
    constexpr bool BFULL = (BN == 128);

    __shared__ uint32_t sAh[2][8][SA], sAl[2][8][SA];
    __shared__ uint32_t sBh[2][8][SB], sBl[2][8][SB];

    const int tid = threadIdx.x, wid = tid >> 5, lane = tid & 31;
    const int g = lane >> 2, t = lane & 3;
    const int wm = (wid / WGN) * WM, wn = (wid % WGN) * WN;
    const int blockRow = blockIdx.y * BM, blockCol = blockIdx.x * BN;

    const int splitk = gridDim.z;
    const int Klocal = Kfull / splitk;
    const int kz = blockIdx.z;

    float acc[MT][NT][4];
#pragma unroll
    for (int i = 0; i < MT; i++)
#pragma unroll
        for (int j = 0; j < NT; j++)
#pragma unroll
            for (int k = 0; k < 4; k++) acc[i][j][k] = 0.f;

    const float* Aptr = A + (size_t)blockRow * Kfull + (size_t)kz * Klocal;
    const float* Bptr = B + (size_t)kz * Klocal * Ndim + blockCol;
    float* Cout = C + (size_t)kz * Mdim * Ndim;

    int ar[LA], aq[LA];
#pragma unroll
    for (int i = 0; i < LA; i++) { int id = tid + i * 256; ar[i] = id >> 2; aq[i] = id & 3; }
    const bool bact = BFULL || (tid < 128);
    const int bk2 = tid / (BN / 4), bn4 = tid % (BN / 4);

    float4 raA[LA], rbB0, rbB1;

    auto loadG = [&](int kt) {
        const int k0 = kt << 4;
#pragma unroll
        for (int i = 0; i < LA; i++)
            raA[i] = *(const float4*)(Aptr + (size_t)ar[i] * Kfull + k0 + aq[i] * 4);
        if (bact) {
            rbB0 = *(const float4*)(Bptr + (size_t)(k0 + 2 * bk2) * Ndim + bn4 * 4);
            rbB1 = *(const float4*)(Bptr + (size_t)(k0 + 2 * bk2 + 1) * Ndim + bn4 * 4);
        }
    };

    auto storeS = [&](int st) {
        uint32_t h, l;
#pragma unroll
        for (int i = 0; i < LA; i++) {
            split_pack_bf(raA[i].x, raA[i].y, h, l);
            sAh[st][aq[i] * 2 + 0][ar[i]] = h; sAl[st][aq[i] * 2 + 0][ar[i]] = l;
            split_pack_bf(raA[i].z, raA[i].w, h, l);
            sAh[st][aq[i] * 2 + 1][ar[i]] = h; sAl[st][aq[i] * 2 + 1][ar[i]] = l;
        }
        if (bact) {
            float b0[4] = {rbB0.x, rbB0.y, rbB0.z, rbB0.w};
            float b1[4] = {rbB1.x, rbB1.y, rbB1.z, rbB1.w};
#pragma unroll
            for (int j = 0; j < 4; j++) {
                split_pack_bf(b0[j], b1[j], h, l);
                sBh[st][bk2][bn4 * 4 + j] = h;
                sBl[st][bk2][bn4 * 4 + j] = l;
            }
        }
    };

    const int nK = Klocal >> 4;
    loadG(0);
    storeS(0);
    __syncthreads();

    int st = 0;
    for (int kt = 0; kt < nK; kt++) {
        const bool more = (kt + 1 < nK);
        if (more) loadG(kt + 1);

        uint32_t ah[MT][4], al[MT][4], bh[NT][2], bl[NT][2];
#pragma unroll
        for (int mt = 0; mt < MT; mt++) {
            int r0 = wm + mt * 16 + g;
            ah[mt][0] = sAh[st][t][r0];
            ah[mt][1] = sAh[st][t][r0 + 8];
            ah[mt][2] = sAh[st][t + 4][r0];
            ah[mt][3] = sAh[st][t + 4][r0 + 8];
            al[mt][0] = sAl[st][t][r0];
            al[mt][1] = sAl[st][t][r0 + 8];
            al[mt][2] = sAl[st][t + 4][r0];
            al[mt][3] = sAl[st][t + 4][r0 + 8];
        }
#pragma unroll
        for (int nt = 0; nt < NT; nt++) {
            int n0 = wn + nt * 8 + g;
            bh[nt][0] = sBh[st][t][n0];
            bh[nt][1] = sBh[st][t + 4][n0];
            bl[nt][0] = sBl[st][t][n0];
            bl[nt][1] = sBl[st][t + 4][n0];
        }
#pragma unroll
        for (int mt = 0; mt < MT; mt++)
#pragma unroll
            for (int nt = 0; nt < NT; nt++) {
                mma16bf(acc[mt][nt], ah[mt], bh[nt]);
                mma16bf(acc[mt][nt], ah[mt], bl[nt]);
                mma16bf(acc[mt][nt], al[mt], bh[nt]);
            }

        if (more) storeS(st ^ 1);
        __syncthreads();
        st ^= 1;
    }

#pragma unroll
    for (int mt = 0; mt < MT; mt++) {
        int r0 = blockRow + wm + mt * 16 + g;
#pragma unroll
        for (int nt = 0; nt < NT; nt++) {
            int c0 = blockCol + wn + nt * 8 + 2 * t;
            *(float2*)(Cout + (size_t)r0 * Ndim + c0) =
                make_float2(acc[mt][nt][0], acc[mt][nt][1]);
            *(float2*)(Cout + (size_t)(r0 + 8) * Ndim + c0) =
                make_float2(acc[mt][nt][2], acc[mt][nt][3]);
        }
    }
}

// ---------------------------------------------------------------------------
// fp16 2-product main GEMM  [R13 verbatim — row-half via pointer offsets]
// ---------------------------------------------------------------------------
template <int BM, int BN, int WGM, int WGN>
__global__ __launch_bounds__(256, 1)
void gemm_fp16_main(const float* __restrict__ A, const float* __restrict__ B,
                    float* __restrict__ C, int Mdim, int Ndim, int Kfull,
                    const float* __restrict__ bias, const float* __restrict__ deg) {
    constexpr int WM = BM / WGM, WN = BN / WGN;
    constexpr int MT = WM / 16, NT = WN / 8;
    constexpr int SA = BM + 8, SB = BN + 8;
    constexpr int LA = BM / 64;

    __shared__ uint32_t sAh[2][8][SA], sAl[2][8][SA];
    __shared__ uint32_t sBh[2][8][SB];

    const int tid = threadIdx.x, wid = tid >> 5, lane = tid & 31;
    const int g = lane >> 2, t = lane & 3;
    const int wm = (wid / WGN) * WM, wn = (wid % WGN) * WN;
    const int blockRow = blockIdx.y * BM, blockCol = blockIdx.x * BN;

    float acc[MT][NT][4];
#pragma unroll
    for (int i = 0; i < MT; i++)
#pragma unroll
        for (int j = 0; j < NT; j++)
#pragma unroll
            for (int k = 0; k < 4; k++) acc[i][j][k] = 0.f;

    const float* Aptr = A + (size_t)blockRow * Kfull;
    const float* Bptr = B + blockCol;

    int ar[LA], aq[LA];
#pragma unroll
    for (int i = 0; i < LA; i++) { int id = tid + i * 256; ar[i] = id >> 2; aq[i] = id & 3; }
    const int bk2 = tid / (BN / 4), bn4 = tid % (BN / 4);

    float4 raA[LA], rbB0, rbB1;

    auto loadG = [&](int kt) {
        const int k0 = kt << 4;
#pragma unroll
        for (int i = 0; i < LA; i++)
            raA[i] = *(const float4*)(Aptr + (size_t)ar[i] * Kfull + k0 + aq[i] * 4);
        rbB0 = *(const float4*)(Bptr + (size_t)(k0 + 2 * bk2) * Ndim + bn4 * 4);
        rbB1 = *(const float4*)(Bptr + (size_t)(k0 + 2 * bk2 + 1) * Ndim + bn4 * 4);
    };

    auto storeS = [&](int st) {
        uint32_t h, l;
#pragma unroll
        for (int i = 0; i < LA; i++) {
            split_pack_h(raA[i].x, raA[i].y, h, l);
            sAh[st][aq[i] * 2 + 0][ar[i]] = h; sAl[st][aq[i] * 2 + 0][ar[i]] = l;
            split_pack_h(raA[i].z, raA[i].w, h, l);
            sAh[st][aq[i] * 2 + 1][ar[i]] = h; sAl[st][aq[i] * 2 + 1][ar[i]] = l;
        }
        {
            float b0[4] = {rbB0.x, rbB0.y, rbB0.z, rbB0.w};
            float b1[4] = {rbB1.x, rbB1.y, rbB1.z, rbB1.w};
#pragma unroll
            for (int j = 0; j < 4; j++)
                sBh[st][bk2][bn4 * 4 + j] = pack_h2(b0[j], b1[j]);
        }
    };

    const int nK = Kfull >> 4;
    loadG(0);
    storeS(0);
    __syncthreads();

    int st = 0;
    for (int kt = 0; kt < nK; kt++) {
        const bool more = (kt + 1 < nK);
        if (more) loadG(kt + 1);

        uint32_t ah[MT][4], al[MT][4], bh[NT][2];
#pragma unroll
        for (int mt = 0; mt < MT; mt++) {
            int r0 = wm + mt * 16 + g;
            ah[mt][0] = sAh[st][t][r0];
            ah[mt][1] = sAh[st][t][r0 + 8];
            ah[mt][2] = sAh[st][t + 4][r0];
            ah[mt][3] = sAh[st][t + 4][r0 + 8];
            al[mt][0] = sAl[st][t][r0];
            al[mt][1] = sAl[st][t][r0 + 8];
            al[mt][2] = sAl[st][t + 4][r0];
            al[mt][3] = sAl[st][t + 4][r0 + 8];
        }
#pragma unroll
        for (int nt = 0; nt < NT; nt++) {
            int n0 = wn + nt * 8 + g;
            bh[nt][0] = sBh[st][t][n0];
            bh[nt][1] = sBh[st][t + 4][n0];
        }
#pragma unroll
        for (int mt = 0; mt < MT; mt++)
#pragma unroll
            for (int nt = 0; nt < NT; nt++) {
                mma16h(acc[mt][nt], ah[mt], bh[nt]);
                mma16h(acc[mt][nt], al[mt], bh[nt]);
            }

        if (more) storeS(st ^ 1);
        __syncthreads();
        st ^= 1;
    }

#pragma unroll
    for (int mt = 0; mt < MT; mt++) {
        int r0 = blockRow + wm + mt * 16 + g;
        float inv0 = 1.0f / deg[r0];
        float inv1 = 1.0f / deg[r0 + 8];
#pragma unroll
        for (int nt = 0; nt < NT; nt++) {
            int c0 = blockCol + wn + nt * 8 + 2 * t;
            float b0 = bias[c0], b1 = bias[c0 + 1];
            float v00 = fmaxf(acc[mt][nt][0] * inv0 + b0, 0.f);
            float v01 = fmaxf(acc[mt][nt][1] * inv0 + b1, 0.f);
            float v10 = fmaxf(acc[mt][nt][2] * inv1 + b0, 0.f);
            float v11 = fmaxf(acc[mt][nt][3] * inv1 + b1, 0.f);
            *(float2*)(C + (size_t)r0 * Ndim + c0)       = make_float2(v00, v01);
            *(float2*)(C + (size_t)(r0 + 8) * Ndim + c0) = make_float2(v10, v11);
        }
    }
}

// ---------------------------------------------------------------------------
// launch: two-phase pipelined fork-join.
//   side:   M-path -> (wait agg0) -> main_half0
//   origin: agg0 -> agg1 -> (wait M) -> main_half1 -> (wait side)
// ---------------------------------------------------------------------------
extern "C" void kernel_launch(void* const* d_in, const int* in_sizes, int n_in,
                              void* d_out, int out_size) {
    const float* nodes = (const float*)d_in[0];
    const float* adj   = (const float*)d_in[1];
    const float* W     = (const float*)d_in[2];
    const float* b     = (const float*)d_in[3];
    const float* K     = (const float*)d_in[4];
    // A_self/A_neigh/num_heads mathematically unused (softmax of row-constant
    // score + adjacency mask == adj/deg exactly, given guaranteed self-loops).

    const int D = in_sizes[3];               // 512
    const int N = in_sizes[0] / D;           // 4096
    const int H = in_sizes[4] / (D * D);     // 4
    float* out = (float*)d_out;

    float *pKbar, *pM, *pMpart, *pc, *pP, *pdeg;
    cudaGetSymbolAddress((void**)&pKbar,  g_Kbar);
    cudaGetSymbolAddress((void**)&pM,     g_M);
    cudaGetSymbolAddress((void**)&pMpart, g_Mpart);
    cudaGetSymbolAddress((void**)&pc,     g_c);
    cudaGetSymbolAddress((void**)&pP,     g_P);
    cudaGetSymbolAddress((void**)&pdeg,   g_deg);

    const int DD4 = D * D / 4;
    const int halfN = N / 2;                 // 2048 rows per half

    static cudaStream_t s2 = nullptr;
    static cudaEvent_t eFork = nullptr, eM = nullptr, eA0 = nullptr, eJoin = nullptr;
    if (s2 == nullptr) {
        cudaStreamCreateWithFlags(&s2, cudaStreamNonBlocking);
        cudaEventCreateWithFlags(&eFork, cudaEventDisableTiming);
        cudaEventCreateWithFlags(&eM,    cudaEventDisableTiming);
        cudaEventCreateWithFlags(&eA0,   cudaEventDisableTiming);
        cudaEventCreateWithFlags(&eJoin, cudaEventDisableTiming);
    }

    // fork
    cudaEventRecord(eFork, 0);
    cudaStreamWaitEvent(s2, eFork, 0);

    // --- side stream: M-path ---
    kbar_kernel<<<(DD4 + 255) / 256, 256, 0, s2>>>(K, H, DD4);
    cvec_part<<<8, 256, 0, s2>>>(b, D);
    {
        dim3 grid(D / 64, D / 64, 4);
        gemm_bf16<64, 64, 2, 4><<<grid, 256, 0, s2>>>(W, pKbar, pMpart, D, D, D);
    }
    reduce_kernel<<<DD4 / 256 + 1, 256, 0, s2>>>(DD4, D);
    cudaEventRecord(eM, s2);

    // --- origin stream: agg half 0 ---
    agg2_kernel<<<halfN / 2, 256>>>(adj, nodes, N, D, 0);
    cudaEventRecord(eA0, 0);

    // --- side stream: main GEMM half 0 (rows 0..halfN) after agg0 + M-path ---
    cudaStreamWaitEvent(s2, eA0, 0);
    {
        dim3 grid(D / 128, halfN / 128, 1);
        gemm_fp16_main<128, 128, 4, 2><<<grid, 256, 0, s2>>>(
            pP, pM, out, N, D, D, pc, pdeg);
    }
    cudaEventRecord(eJoin, s2);

    // --- origin stream: agg half 1, then main GEMM half 1 ---
    agg2_kernel<<<halfN / 2, 256>>>(adj, nodes, N, D, halfN);
    cudaStreamWaitEvent(0, eM, 0);
    {
        dim3 grid(D / 128, halfN / 128, 1);
        gemm_fp16_main<128, 128, 4, 2><<<grid, 256>>>(
            pP + (size_t)halfN * D, pM, out + (size_t)halfN * D,
            N, D, D, pc, pdeg + halfN);
    }

    // join side stream back into origin before capture ends
    cudaStreamWaitEvent(0, eJoin, 0);
    (void)n_in; (void)out_size;
}

// round 16
// speedup vs baseline: 1.0851x; 1.0851x over previous
#include <cuda_runtime.h>
#include <cuda_bf16.h>
#include <cuda_fp16.h>
#include <cstdint>

#define MAXN 4096
#define MAXD 512

__device__ __align__(16) float g_Kbar[MAXD * MAXD];
__device__ __align__(16) float g_M[MAXD * MAXD];
__device__ __align__(16) float g_Mpart[4 * MAXD * MAXD];
__device__ __align__(16) float g_c[MAXD];
__device__ __align__(16) float g_cpart[8 * MAXD];
__device__ __align__(16) float g_P[MAXN * MAXD];
__device__ float g_deg[MAXN];

// ---------------------------------------------------------------------------
// helpers  [R13/R14 verbatim]
// ---------------------------------------------------------------------------
__device__ __forceinline__ void mma16bf(float* d, const uint32_t* a, const uint32_t* b) {
    asm volatile(
        "mma.sync.aligned.m16n8k16.row.col.f32.bf16.bf16.f32 "
        "{%0,%1,%2,%3},{%4,%5,%6,%7},{%8,%9},{%0,%1,%2,%3};\n"
        : "+f"(d[0]), "+f"(d[1]), "+f"(d[2]), "+f"(d[3])
        : "r"(a[0]), "r"(a[1]), "r"(a[2]), "r"(a[3]), "r"(b[0]), "r"(b[1]));
}

__device__ __forceinline__ void mma16h(float* d, const uint32_t* a, const uint32_t* b) {
    asm volatile(
        "mma.sync.aligned.m16n8k16.row.col.f32.f16.f16.f32 "
        "{%0,%1,%2,%3},{%4,%5,%6,%7},{%8,%9},{%0,%1,%2,%3};\n"
        : "+f"(d[0]), "+f"(d[1]), "+f"(d[2]), "+f"(d[3])
        : "r"(a[0]), "r"(a[1]), "r"(a[2]), "r"(a[3]), "r"(b[0]), "r"(b[1]));
}

__device__ __forceinline__ void split_pack_bf(float x0, float x1,
                                              uint32_t& h, uint32_t& l) {
    __nv_bfloat16 h0 = __float2bfloat16(x0), h1 = __float2bfloat16(x1);
    float r0 = x0 - __bfloat162float(h0);
    float r1 = x1 - __bfloat162float(h1);
    __nv_bfloat16 l0 = __float2bfloat16(r0), l1 = __float2bfloat16(r1);
    __nv_bfloat162 hp; hp.x = h0; hp.y = h1;
    __nv_bfloat162 lp; lp.x = l0; lp.y = l1;
    h = *(uint32_t*)&hp;
    l = *(uint32_t*)&lp;
}

__device__ __forceinline__ uint32_t pack_h2(float x0, float x1) {
    __half2 p = __floats2half2_rn(x0, x1);
    return *(uint32_t*)&p;
}

// ---------------------------------------------------------------------------
// Kbar = mean over heads  [R14 verbatim]
// ---------------------------------------------------------------------------
__global__ void kbar_kernel(const float* __restrict__ K, int H, int DD4) {
    int i = blockIdx.x * blockDim.x + threadIdx.x;
    if (i < DD4) {
        const float4* K4 = (const float4*)K;
        float4 s = make_float4(0, 0, 0, 0);
        for (int h = 0; h < H; h++) {
            float4 x = K4[(size_t)h * DD4 + i];
            s.x += x.x; s.y += x.y; s.z += x.z; s.w += x.w;
        }
        float inv = 1.0f / (float)H;
        ((float4*)g_Kbar)[i] = make_float4(s.x * inv, s.y * inv, s.z * inv, s.w * inv);
    }
}

// ---------------------------------------------------------------------------
// cvec partials from g_Kbar  [R14 verbatim]
// ---------------------------------------------------------------------------
__global__ void cvec_part(const float* __restrict__ b, int D) {
    const int p = blockIdx.x;
    const int tid = threadIdx.x;
    const int dlo = p * (D / 8), dhi = dlo + D / 8;
    float a0 = 0.f, a1 = 0.f;
    for (int d = dlo; d < dhi; d++) {
        float bd = b[d];
        a0 += bd * g_Kbar[(size_t)d * D + tid];
        a1 += bd * g_Kbar[(size_t)d * D + tid + 256];
    }
    g_cpart[p * D + tid] = a0;
    g_cpart[p * D + tid + 256] = a1;
}

// ---------------------------------------------------------------------------
// fused reduce  [R14 verbatim]
// ---------------------------------------------------------------------------
__global__ void reduce_kernel(int DD4, int D) {
    const int nb = DD4 / 256;
    if ((int)blockIdx.x < nb) {
        int i = blockIdx.x * 256 + threadIdx.x;
        const float4* P4 = (const float4*)g_Mpart;
        float4 s = P4[i];
#pragma unroll
        for (int z = 1; z < 4; z++) {
            float4 x = P4[(size_t)z * DD4 + i];
            s.x += x.x; s.y += x.y; s.z += x.z; s.w += x.w;
        }
        ((float4*)g_M)[i] = s;
    } else {
        int f0 = threadIdx.x * 2;
#pragma unroll
        for (int q = 0; q < 2; q++) {
            int f = f0 + q;
            float s = 0.f;
            for (int p = 0; p < 8; p++) s += g_cpart[p * D + f];
            g_c[f] = s;
        }
    }
}

// ---------------------------------------------------------------------------
// Sparse aggregation, 2 rows per block  [R14 verbatim]
// ---------------------------------------------------------------------------
__global__ void agg2_kernel(const float* __restrict__ adj,
                            const float* __restrict__ nodes,
                            int n, int d) {
    __shared__ int s_idx[2][4096];
    __shared__ int s_cnt[8];
    const int tid  = threadIdx.x;
    const int w    = tid >> 5;
    const int lane = tid & 31;
    const unsigned mlt = (1u << lane) - 1u;

    const int rsel = w >> 2;
    const int wseg = w & 3;
    const int row  = blockIdx.x * 2 + rsel;
    const int segN = n >> 2;
    const int base = wseg * segN;
    const float* arow = adj + (size_t)row * n;

    int cnt = 0;
    for (int s = 0; s < segN; s += 128) {
        int c0 = base + s + lane * 4;
        float4 v = *(const float4*)(arow + c0);
        unsigned m;
        m = __ballot_sync(0xffffffffu, v.x > 0.5f);
        if (v.x > 0.5f) s_idx[rsel][base + cnt + __popc(m & mlt)] = c0;
        cnt += __popc(m);
        m = __ballot_sync(0xffffffffu, v.y > 0.5f);
        if (v.y > 0.5f) s_idx[rsel][base + cnt + __popc(m & mlt)] = c0 + 1;
        cnt += __popc(m);
        m = __ballot_sync(0xffffffffu, v.z > 0.5f);
        if (v.z > 0.5f) s_idx[rsel][base + cnt + __popc(m & mlt)] = c0 + 2;
        cnt += __popc(m);
        m = __ballot_sync(0xffffffffu, v.w > 0.5f);
        if (v.w > 0.5f) s_idx[rsel][base + cnt + __popc(m & mlt)] = c0 + 3;
        cnt += __popc(m);
    }
    if (lane == 0) s_cnt[w] = cnt;
    __syncthreads();

    if (tid < 2) {
        int dg = 0;
#pragma unroll
        for (int i = 0; i < 4; i++) dg += s_cnt[tid * 4 + i];
        g_deg[blockIdx.x * 2 + tid] = (float)dg;
    }

    const int gr   = tid >> 7;
    const int gl   = tid & 127;
    const int grow = blockIdx.x * 2 + gr;
    const int d4 = d >> 2;
    const float4* nodes4 = (const float4*)nodes;
    float4* P4 = (float4*)g_P;

    for (int col = gl; col < d4; col += 128) {
        float4 acc = make_float4(0.f, 0.f, 0.f, 0.f);
        for (int ww = 0; ww < 4; ww++) {
            const int  c   = s_cnt[gr * 4 + ww];
            const int* lst = s_idx[gr] + ww * segN;
            for (int k = 0; k < c; k++) {
                int j = lst[k];
                float4 t = nodes4[(size_t)j * d4 + col];
                acc.x += t.x; acc.y += t.y; acc.z += t.z; acc.w += t.w;
            }
        }
        P4[(size_t)grow * d4 + col] = acc;
    }
}

// ---------------------------------------------------------------------------
// bf16-split 3-product GEMM  [R14 verbatim — M = W @ Kbar]
// ---------------------------------------------------------------------------
template <int BM, int BN, int WGM, int WGN>
__global__ __launch_bounds__(256, 1)
void gemm_bf16(const float* __restrict__ A, const float* __restrict__ B,
               float* __restrict__ C, int Mdim, int Ndim, int Kfull) {
    constexpr int WM = BM / WGM, WN = BN / WGN;
    constexpr int MT = WM / 16, NT = WN / 8;
    constexpr int SA = BM + 8, SB = BN + 8;
    constexpr int LA = BM / 64;
    constexpr bool BFULL = (BN == 128);

    __shared__ uint32_t sAh[2][8][SA], sAl[2][8][SA];
    __shared__ uint32_t sBh[2][8][SB], sBl[2][8][SB];

    const int tid = threadIdx.x, wid = tid >> 5, lane = tid & 31;
    const int g = lane >> 2, t = lane & 3;
    const int wm = (wid / WGN) * WM, wn = (wid % WGN) * WN;
    const int blockRow = blockIdx.y * BM, blockCol = blockIdx.x * BN;

    const int splitk = gridDim.z;
    const int Klocal = Kfull / splitk;
    const int kz = blockIdx.z;

    float acc[MT][NT][4];
#pragma unroll
    for (int i = 0; i < MT; i++)
#pragma unroll
        for (int j = 0; j < NT; j++)
#pragma unroll
            for (int k = 0; k < 4; k++) acc[i][j][k] = 0.f;

    const float* Aptr = A + (size_t)blockRow * Kfull + (size_t)kz * Klocal;
    const float* Bptr = B + (size_t)kz * Klocal * Ndim + blockCol;
    float* Cout = C + (size_t)kz * Mdim * Ndim;

    int ar[LA], aq[LA];
#pragma unroll
    for (int i = 0; i < LA; i++) { int id = tid + i * 256; ar[i] = id >> 2; aq[i] = id & 3; }
    const bool bact = BFULL || (tid < 128);
    const int bk2 = tid / (BN / 4), bn4 = tid % (BN / 4);

    float4 raA[LA], rbB0, rbB1;

    auto loadG = [&](int kt) {
        const int k0 = kt << 4;
#pragma unroll
        for (int i = 0; i < LA; i++)
            raA[i] = *(const float4*)(Aptr + (size_t)ar[i] * Kfull + k0 + aq[i] * 4);
        if (bact) {
            rbB0 = *(const float4*)(Bptr + (size_t)(k0 + 2 * bk2) * Ndim + bn4 * 4);
            rbB1 = *(const float4*)(Bptr + (size_t)(k0 + 2 * bk2 + 1) * Ndim + bn4 * 4);
        }
    };

    auto storeS = [&](int st) {
        uint32_t h, l;
#pragma unroll
        for (int i = 0; i < LA; i++) {
            split_pack_bf(raA[i].x, raA[i].y, h, l);
            sAh[st][aq[i] * 2 + 0][ar[i]] = h; sAl[st][aq[i] * 2 + 0][ar[i]] = l;
            split_pack_bf(raA[i].z, raA[i].w, h, l);
            sAh[st][aq[i] * 2 + 1][ar[i]] = h; sAl[st][aq[i] * 2 + 1][ar[i]] = l;
        }
        if (bact) {
            float b0[4] = {rbB0.x, rbB0.y, rbB0.z, rbB0.w};
            float b1[4] = {rbB1.x, rbB1.y, rbB1.z, rbB1.w};
#pragma unroll
            for (int j = 0; j < 4; j++) {
                split_pack_bf(b0[j], b1[j], h, l);
                sBh[st][bk2][bn4 * 4 + j] = h;
                sBl[st][bk2][bn4 * 4 + j] = l;
            }
        }
    };

    const int nK = Klocal >> 4;
    loadG(0);
    storeS(0);
    __syncthreads();

    int st = 0;
    for (int kt = 0; kt < nK; kt++) {
        const bool more = (kt + 1 < nK);
        if (more) loadG(kt + 1);

        uint32_t ah[MT][4], al[MT][4], bh[NT][2], bl[NT][2];
#pragma unroll
        for (int mt = 0; mt < MT; mt++) {
            int r0 = wm + mt * 16 + g;
            ah[mt][0] = sAh[st][t][r0];
            ah[mt][1] = sAh[st][t][r0 + 8];
            ah[mt][2] = sAh[st][t + 4][r0];
            ah[mt][3] = sAh[st][t + 4][r0 + 8];
            al[mt][0] = sAl[st][t][r0];
            al[mt][1] = sAl[st][t][r0 + 8];
            al[mt][2] = sAl[st][t + 4][r0];
            al[mt][3] = sAl[st][t + 4][r0 + 8];
        }
#pragma unroll
        for (int nt = 0; nt < NT; nt++) {
            int n0 = wn + nt * 8 + g;
            bh[nt][0] = sBh[st][t][n0];
            bh[nt][1] = sBh[st][t + 4][n0];
            bl[nt][0] = sBl[st][t][n0];
            bl[nt][1] = sBl[st][t + 4][n0];
        }
#pragma unroll
        for (int mt = 0; mt < MT; mt++)
#pragma unroll
            for (int nt = 0; nt < NT; nt++) {
                mma16bf(acc[mt][nt], ah[mt], bh[nt]);
                mma16bf(acc[mt][nt], ah[mt], bl[nt]);
                mma16bf(acc[mt][nt], al[mt], bh[nt]);
            }

        if (more) storeS(st ^ 1);
        __syncthreads();
        st ^= 1;
    }

#pragma unroll
    for (int mt = 0; mt < MT; mt++) {
        int r0 = blockRow + wm + mt * 16 + g;
#pragma unroll
        for (int nt = 0; nt < NT; nt++) {
            int c0 = blockCol + wn + nt * 8 + 2 * t;
            *(float2*)(Cout + (size_t)r0 * Ndim + c0) =
                make_float2(acc[mt][nt][0], acc[mt][nt][1]);
            *(float2*)(Cout + (size_t)(r0 + 8) * Ndim + c0) =
                make_float2(acc[mt][nt][2], acc[mt][nt][3]);
        }
    }
}

// ---------------------------------------------------------------------------
// fp16 SINGLE-product main GEMM: A=P rounded once, B=M rounded once.
// D = fp16(P)·fp16(M); error ~3e-4 rel (two independent fp16 roundings).
// Structure = R13 kernel minus the lo plane (sAl/al/2nd mma deleted).
// Epilogue: relu(acc/deg + bias).
// ---------------------------------------------------------------------------
template <int BM, int BN, int WGM, int WGN>
__global__ __launch_bounds__(256, 1)
void gemm_fp16_main(const float* __restrict__ A, const float* __restrict__ B,
                    float* __restrict__ C, int Mdim, int Ndim, int Kfull,
                    const float* __restrict__ bias, const float* __restrict__ deg) {
    constexpr int WM = BM / WGM, WN = BN / WGN;
    constexpr int MT = WM / 16, NT = WN / 8;
    constexpr int SA = BM + 8, SB = BN + 8;
    constexpr int LA = BM / 64;

    __shared__ uint32_t sAh[2][8][SA];
    __shared__ uint32_t sBh[2][8][SB];

    const int tid = threadIdx.x, wid = tid >> 5, lane = tid & 31;
    const int g = lane >> 2, t = lane & 3;
    const int wm = (wid / WGN) * WM, wn = (wid % WGN) * WN;
    const int blockRow = blockIdx.y * BM, blockCol = blockIdx.x * BN;

    float acc[MT][NT][4];
#pragma unroll
    for (int i = 0; i < MT; i++)
#pragma unroll
        for (int j = 0; j < NT; j++)
#pragma unroll
            for (int k = 0; k < 4; k++) acc[i][j][k] = 0.f;

    const float* Aptr = A + (size_t)blockRow * Kfull;
    const float* Bptr = B + blockCol;

    int ar[LA], aq[LA];
#pragma unroll
    for (int i = 0; i < LA; i++) { int id = tid + i * 256; ar[i] = id >> 2; aq[i] = id & 3; }
    const int bk2 = tid / (BN / 4), bn4 = tid % (BN / 4);

    float4 raA[LA], rbB0, rbB1;

    auto loadG = [&](int kt) {
        const int k0 = kt << 4;
#pragma unroll
        for (int i = 0; i < LA; i++)
            raA[i] = *(const float4*)(Aptr + (size_t)ar[i] * Kfull + k0 + aq[i] * 4);
        rbB0 = *(const float4*)(Bptr + (size_t)(k0 + 2 * bk2) * Ndim + bn4 * 4);
        rbB1 = *(const float4*)(Bptr + (size_t)(k0 + 2 * bk2 + 1) * Ndim + bn4 * 4);
    };

    auto storeS = [&](int st) {
#pragma unroll
        for (int i = 0; i < LA; i++) {
            sAh[st][aq[i] * 2 + 0][ar[i]] = pack_h2(raA[i].x, raA[i].y);
            sAh[st][aq[i] * 2 + 1][ar[i]] = pack_h2(raA[i].z, raA[i].w);
        }
        {
            float b0[4] = {rbB0.x, rbB0.y, rbB0.z, rbB0.w};
            float b1[4] = {rbB1.x, rbB1.y, rbB1.z, rbB1.w};
#pragma unroll
            for (int j = 0; j < 4; j++)
                sBh[st][bk2][bn4 * 4 + j] = pack_h2(b0[j], b1[j]);
        }
    };

    const int nK = Kfull >> 4;
    loadG(0);
    storeS(0);
    __syncthreads();

    int st = 0;
    for (int kt = 0; kt < nK; kt++) {
        const bool more = (kt + 1 < nK);
        if (more) loadG(kt + 1);

        uint32_t ah[MT][4], bh[NT][2];
#pragma unroll
        for (int mt = 0; mt < MT; mt++) {
            int r0 = wm + mt * 16 + g;
            ah[mt][0] = sAh[st][t][r0];
            ah[mt][1] = sAh[st][t][r0 + 8];
            ah[mt][2] = sAh[st][t + 4][r0];
            ah[mt][3] = sAh[st][t + 4][r0 + 8];
        }
#pragma unroll
        for (int nt = 0; nt < NT; nt++) {
            int n0 = wn + nt * 8 + g;
            bh[nt][0] = sBh[st][t][n0];
            bh[nt][1] = sBh[st][t + 4][n0];
        }
#pragma unroll
        for (int mt = 0; mt < MT; mt++)
#pragma unroll
            for (int nt = 0; nt < NT; nt++)
                mma16h(acc[mt][nt], ah[mt], bh[nt]);

        if (more) storeS(st ^ 1);
        __syncthreads();
        st ^= 1;
    }

#pragma unroll
    for (int mt = 0; mt < MT; mt++) {
        int r0 = blockRow + wm + mt * 16 + g;
        float inv0 = 1.0f / deg[r0];
        float inv1 = 1.0f / deg[r0 + 8];
#pragma unroll
        for (int nt = 0; nt < NT; nt++) {
            int c0 = blockCol + wn + nt * 8 + 2 * t;
            float b0 = bias[c0], b1 = bias[c0 + 1];
            float v00 = fmaxf(acc[mt][nt][0] * inv0 + b0, 0.f);
            float v01 = fmaxf(acc[mt][nt][1] * inv0 + b1, 0.f);
            float v10 = fmaxf(acc[mt][nt][2] * inv1 + b0, 0.f);
            float v11 = fmaxf(acc[mt][nt][3] * inv1 + b1, 0.f);
            *(float2*)(C + (size_t)r0 * Ndim + c0)       = make_float2(v00, v01);
            *(float2*)(C + (size_t)(r0 + 8) * Ndim + c0) = make_float2(v10, v11);
        }
    }
}

// ---------------------------------------------------------------------------
// launch: R14 fork-join schedule verbatim.
//   side:   kbar -> cvec -> M-GEMM -> reduce
//   origin: agg  -> (wait side) -> main GEMM
// ---------------------------------------------------------------------------
extern "C" void kernel_launch(void* const* d_in, const int* in_sizes, int n_in,
                              void* d_out, int out_size) {
    const float* nodes = (const float*)d_in[0];
    const float* adj   = (const float*)d_in[1];
    const float* W     = (const float*)d_in[2];
    const float* b     = (const float*)d_in[3];
    const float* K     = (const float*)d_in[4];
    // A_self/A_neigh/num_heads mathematically unused (softmax of row-constant
    // score + adjacency mask == adj/deg exactly, given guaranteed self-loops).

    const int D = in_sizes[3];               // 512
    const int N = in_sizes[0] / D;           // 4096
    const int H = in_sizes[4] / (D * D);     // 4
    float* out = (float*)d_out;

    float *pKbar, *pM, *pMpart, *pc, *pP, *pdeg;
    cudaGetSymbolAddress((void**)&pKbar,  g_Kbar);
    cudaGetSymbolAddress((void**)&pM,     g_M);
    cudaGetSymbolAddress((void**)&pMpart, g_Mpart);
    cudaGetSymbolAddress((void**)&pc,     g_c);
    cudaGetSymbolAddress((void**)&pP,     g_P);
    cudaGetSymbolAddress((void**)&pdeg,   g_deg);

    const int DD4 = D * D / 4;

    static cudaStream_t s2 = nullptr;
    static cudaEvent_t eFork = nullptr, eJoin = nullptr;
    if (s2 == nullptr) {
        cudaStreamCreateWithFlags(&s2, cudaStreamNonBlocking);
        cudaEventCreateWithFlags(&eFork, cudaEventDisableTiming);
        cudaEventCreateWithFlags(&eJoin, cudaEventDisableTiming);
    }

    // fork
    cudaEventRecord(eFork, 0);
    cudaStreamWaitEvent(s2, eFork, 0);

    // --- side stream: M-path ---
    kbar_kernel<<<(DD4 + 255) / 256, 256, 0, s2>>>(K, H, DD4);
    cvec_part<<<8, 256, 0, s2>>>(b, D);
    {
        dim3 grid(D / 64, D / 64, 4);
        gemm_bf16<64, 64, 2, 4><<<grid, 256, 0, s2>>>(W, pKbar, pMpart, D, D, D);
    }
    reduce_kernel<<<DD4 / 256 + 1, 256, 0, s2>>>(DD4, D);
    cudaEventRecord(eJoin, s2);

    // --- origin stream: sparse aggregation ---
    agg2_kernel<<<N / 2, 256>>>(adj, nodes, N, D);

    // join, then main GEMM
    cudaStreamWaitEvent(0, eJoin, 0);
    {
        dim3 grid(D / 128, N / 128, 1);
        gemm_fp16_main<128, 128, 4, 2><<<grid, 256>>>(pP, pM, out,
                                                      N, D, D, pc, pdeg);
    }
    (void)n_in; (void)out_size;
}

// round 17
// speedup vs baseline: 1.2516x; 1.1534x over previous
#include <cuda_runtime.h>
#include <cuda_bf16.h>
#include <cuda_fp16.h>
#include <cstdint>

#define MAXN 4096
#define MAXD 512

__device__ __align__(16) float g_Kbar[MAXD * MAXD];
__device__ __align__(16) float g_M[MAXD * MAXD];
__device__ __align__(16) float g_Mpart[4 * MAXD * MAXD];
__device__ __align__(16) float g_c[MAXD];
__device__ __align__(16) float g_cpart[8 * MAXD];
__device__ __align__(16) uint32_t g_nodesH[MAXN * MAXD / 2];  // nodes, packed fp16
__device__ __align__(16) uint32_t g_Ph[MAXN * MAXD / 2];      // P, packed fp16
__device__ float g_deg[MAXN];

// ---------------------------------------------------------------------------
// helpers
// ---------------------------------------------------------------------------
__device__ __forceinline__ void mma16bf(float* d, const uint32_t* a, const uint32_t* b) {
    asm volatile(
        "mma.sync.aligned.m16n8k16.row.col.f32.bf16.bf16.f32 "
        "{%0,%1,%2,%3},{%4,%5,%6,%7},{%8,%9},{%0,%1,%2,%3};\n"
        : "+f"(d[0]), "+f"(d[1]), "+f"(d[2]), "+f"(d[3])
        : "r"(a[0]), "r"(a[1]), "r"(a[2]), "r"(a[3]), "r"(b[0]), "r"(b[1]));
}

__device__ __forceinline__ void mma16h(float* d, const uint32_t* a, const uint32_t* b) {
    asm volatile(
        "mma.sync.aligned.m16n8k16.row.col.f32.f16.f16.f32 "
        "{%0,%1,%2,%3},{%4,%5,%6,%7},{%8,%9},{%0,%1,%2,%3};\n"
        : "+f"(d[0]), "+f"(d[1]), "+f"(d[2]), "+f"(d[3])
        : "r"(a[0]), "r"(a[1]), "r"(a[2]), "r"(a[3]), "r"(b[0]), "r"(b[1]));
}

__device__ __forceinline__ void split_pack_bf(float x0, float x1,
                                              uint32_t& h, uint32_t& l) {
    __nv_bfloat16 h0 = __float2bfloat16(x0), h1 = __float2bfloat16(x1);
    float r0 = x0 - __bfloat162float(h0);
    float r1 = x1 - __bfloat162float(h1);
    __nv_bfloat16 l0 = __float2bfloat16(r0), l1 = __float2bfloat16(r1);
    __nv_bfloat162 hp; hp.x = h0; hp.y = h1;
    __nv_bfloat162 lp; lp.x = l0; lp.y = l1;
    h = *(uint32_t*)&hp;
    l = *(uint32_t*)&lp;
}

__device__ __forceinline__ uint32_t pack_h2(float x0, float x1) {
    __half2 p = __floats2half2_rn(x0, x1);
    return *(uint32_t*)&p;
}

// ---------------------------------------------------------------------------
// nodes -> packed fp16 (single rounding)
// ---------------------------------------------------------------------------
__global__ void nodes2h_kernel(const float* __restrict__ nodes, int total2) {
    int i = blockIdx.x * blockDim.x + threadIdx.x;
    if (i < total2) {
        float2 v = ((const float2*)nodes)[i];
        g_nodesH[i] = pack_h2(v.x, v.y);
    }
}

// ---------------------------------------------------------------------------
// Kbar = mean over heads  [R14 verbatim]
// ---------------------------------------------------------------------------
__global__ void kbar_kernel(const float* __restrict__ K, int H, int DD4) {
    int i = blockIdx.x * blockDim.x + threadIdx.x;
    if (i < DD4) {
        const float4* K4 = (const float4*)K;
        float4 s = make_float4(0, 0, 0, 0);
        for (int h = 0; h < H; h++) {
            float4 x = K4[(size_t)h * DD4 + i];
            s.x += x.x; s.y += x.y; s.z += x.z; s.w += x.w;
        }
        float inv = 1.0f / (float)H;
        ((float4*)g_Kbar)[i] = make_float4(s.x * inv, s.y * inv, s.z * inv, s.w * inv);
    }
}

// ---------------------------------------------------------------------------
// cvec partials from g_Kbar  [R14 verbatim]
// ---------------------------------------------------------------------------
__global__ void cvec_part(const float* __restrict__ b, int D) {
    const int p = blockIdx.x;
    const int tid = threadIdx.x;
    const int dlo = p * (D / 8), dhi = dlo + D / 8;
    float a0 = 0.f, a1 = 0.f;
    for (int d = dlo; d < dhi; d++) {
        float bd = b[d];
        a0 += bd * g_Kbar[(size_t)d * D + tid];
        a1 += bd * g_Kbar[(size_t)d * D + tid + 256];
    }
    g_cpart[p * D + tid] = a0;
    g_cpart[p * D + tid + 256] = a1;
}

// ---------------------------------------------------------------------------
// fused reduce  [R14 verbatim]
// ---------------------------------------------------------------------------
__global__ void reduce_kernel(int DD4, int D) {
    const int nb = DD4 / 256;
    if ((int)blockIdx.x < nb) {
        int i = blockIdx.x * 256 + threadIdx.x;
        const float4* P4 = (const float4*)g_Mpart;
        float4 s = P4[i];
#pragma unroll
        for (int z = 1; z < 4; z++) {
            float4 x = P4[(size_t)z * DD4 + i];
            s.x += x.x; s.y += x.y; s.z += x.z; s.w += x.w;
        }
        ((float4*)g_M)[i] = s;
    } else {
        int f0 = threadIdx.x * 2;
#pragma unroll
        for (int q = 0; q < 2; q++) {
            int f = f0 + q;
            float s = 0.f;
            for (int p = 0; p < 8; p++) s += g_cpart[p * D + f];
            g_c[f] = s;
        }
    }
}

// ---------------------------------------------------------------------------
// Sparse aggregation, 2 rows per block. Scan R14-verbatim; gather reads
// packed fp16 nodes (uint2 = 4 halfs per thread), accumulates in fp32
// (same serial order -> deterministic), stores P as packed fp16.
// ---------------------------------------------------------------------------
__global__ void agg2_kernel(const float* __restrict__ adj, int n, int d) {
    __shared__ int s_idx[2][4096];
    __shared__ int s_cnt[8];
    const int tid  = threadIdx.x;
    const int w    = tid >> 5;
    const int lane = tid & 31;
    const unsigned mlt = (1u << lane) - 1u;

    const int rsel = w >> 2;
    const int wseg = w & 3;
    const int row  = blockIdx.x * 2 + rsel;
    const int segN = n >> 2;
    const int base = wseg * segN;
    const float* arow = adj + (size_t)row * n;

    int cnt = 0;
    for (int s = 0; s < segN; s += 128) {
        int c0 = base + s + lane * 4;
        float4 v = *(const float4*)(arow + c0);
        unsigned m;
        m = __ballot_sync(0xffffffffu, v.x > 0.5f);
        if (v.x > 0.5f) s_idx[rsel][base + cnt + __popc(m & mlt)] = c0;
        cnt += __popc(m);
        m = __ballot_sync(0xffffffffu, v.y > 0.5f);
        if (v.y > 0.5f) s_idx[rsel][base + cnt + __popc(m & mlt)] = c0 + 1;
        cnt += __popc(m);
        m = __ballot_sync(0xffffffffu, v.z > 0.5f);
        if (v.z > 0.5f) s_idx[rsel][base + cnt + __popc(m & mlt)] = c0 + 2;
        cnt += __popc(m);
        m = __ballot_sync(0xffffffffu, v.w > 0.5f);
        if (v.w > 0.5f) s_idx[rsel][base + cnt + __popc(m & mlt)] = c0 + 3;
        cnt += __popc(m);
    }
    if (lane == 0) s_cnt[w] = cnt;
    __syncthreads();

    if (tid < 2) {
        int dg = 0;
#pragma unroll
        for (int i = 0; i < 4; i++) dg += s_cnt[tid * 4 + i];
        g_deg[blockIdx.x * 2 + tid] = (float)dg;
    }

    const int gr   = tid >> 7;
    const int gl   = tid & 127;
    const int grow = blockIdx.x * 2 + gr;
    const int d2 = d >> 2;                    // uint2 per row (128)
    const uint2* nodesH = (const uint2*)g_nodesH;
    uint2* Ph = (uint2*)g_Ph;

    for (int col = gl; col < d2; col += 128) {
        float4 acc = make_float4(0.f, 0.f, 0.f, 0.f);
        for (int ww = 0; ww < 4; ww++) {
            const int  c   = s_cnt[gr * 4 + ww];
            const int* lst = s_idx[gr] + ww * segN;
            for (int k = 0; k < c; k++) {
                int j = lst[k];
                uint2 t = nodesH[(size_t)j * d2 + col];
                float2 f0 = __half22float2(*(__half2*)&t.x);
                float2 f1 = __half22float2(*(__half2*)&t.y);
                acc.x += f0.x; acc.y += f0.y; acc.z += f1.x; acc.w += f1.y;
            }
        }
        uint2 o;
        o.x = pack_h2(acc.x, acc.y);
        o.y = pack_h2(acc.z, acc.w);
        Ph[(size_t)grow * d2 + col] = o;
    }
}

// ---------------------------------------------------------------------------
// bf16-split 3-product GEMM  [R14 verbatim — M = W @ Kbar]
// ---------------------------------------------------------------------------
template <int BM, int BN, int WGM, int WGN>
__global__ __launch_bounds__(256, 1)
void gemm_bf16(const float* __restrict__ A, const float* __restrict__ B,
               float* __restrict__ C, int Mdim, int Ndim, int Kfull) {
    constexpr int WM = BM / WGM, WN = BN / WGN;
    constexpr int MT = WM / 16, NT = WN / 8;
    constexpr int SA = BM + 8, SB = BN + 8;
    constexpr int LA = BM / 64;
    constexpr bool BFULL = (BN == 128);

    __shared__ uint32_t sAh[2][8][SA], sAl[2][8][SA];
    __shared__ uint32_t sBh[2][8][SB], sBl[2][8][SB];

    const int tid = threadIdx.x, wid = tid >> 5, lane = tid & 31;
    const int g = lane >> 2, t = lane & 3;
    const int wm = (wid / WGN) * WM, wn = (wid % WGN) * WN;
    const int blockRow = blockIdx.y * BM, blockCol = blockIdx.x * BN;

    const int splitk = gridDim.z;
    const int Klocal = Kfull / splitk;
    const int kz = blockIdx.z;

    float acc[MT][NT][4];
#pragma unroll
    for (int i = 0; i < MT; i++)
#pragma unroll
        for (int j = 0; j < NT; j++)
#pragma unroll
            for (int k = 0; k < 4; k++) acc[i][j][k] = 0.f;

    const float* Aptr = A + (size_t)blockRow * Kfull + (size_t)kz * Klocal;
    const float* Bptr = B + (size_t)kz * Klocal * Ndim + blockCol;
    float* Cout = C + (size_t)kz * Mdim * Ndim;

    int ar[LA], aq[LA];
#pragma unroll
    for (int i = 0; i < LA; i++) { int id = tid + i * 256; ar[i] = id >> 2; aq[i] = id & 3; }
    const bool bact = BFULL || (tid < 128);
    const int bk2 = tid / (BN / 4), bn4 = tid % (BN / 4);

    float4 raA[LA], rbB0, rbB1;

    auto loadG = [&](int kt) {
        const int k0 = kt << 4;
#pragma unroll
        for (int i = 0; i < LA; i++)
            raA[i] = *(const float4*)(Aptr + (size_t)ar[i] * Kfull + k0 + aq[i] * 4);
        if (bact) {
            rbB0 = *(const float4*)(Bptr + (size_t)(k0 + 2 * bk2) * Ndim + bn4 * 4);
            rbB1 = *(const float4*)(Bptr + (size_t)(k0 + 2 * bk2 + 1) * Ndim + bn4 * 4);
        }
    };

    auto storeS = [&](int st) {
        uint32_t h, l;
#pragma unroll
        for (int i = 0; i < LA; i++) {
            split_pack_bf(raA[i].x, raA[i].y, h, l);
            sAh[st][aq[i] * 2 + 0][ar[i]] = h; sAl[st][aq[i] * 2 + 0][ar[i]] = l;
            split_pack_bf(raA[i].z, raA[i].w, h, l);
            sAh[st][aq[i] * 2 + 1][ar[i]] = h; sAl[st][aq[i] * 2 + 1][ar[i]] = l;
        }
        if (bact) {
            float b0[4] = {rbB0.x, rbB0.y, rbB0.z, rbB0.w};
            float b1[4] = {rbB1.x, rbB1.y, rbB1.z, rbB1.w};
#pragma unroll
            for (int j = 0; j < 4; j++) {
                split_pack_bf(b0[j], b1[j], h, l);
                sBh[st][bk2][bn4 * 4 + j] = h;
                sBl[st][bk2][bn4 * 4 + j] = l;
            }
        }
    };

    const int nK = Klocal >> 4;
    loadG(0);
    storeS(0);
    __syncthreads();

    int st = 0;
    for (int kt = 0; kt < nK; kt++) {
        const bool more = (kt + 1 < nK);
        if (more) loadG(kt + 1);

        uint32_t ah[MT][4], al[MT][4], bh[NT][2], bl[NT][2];
#pragma unroll
        for (int mt = 0; mt < MT; mt++) {
            int r0 = wm + mt * 16 + g;
            ah[mt][0] = sAh[st][t][r0];
            ah[mt][1] = sAh[st][t][r0 + 8];
            ah[mt][2] = sAh[st][t + 4][r0];
            ah[mt][3] = sAh[st][t + 4][r0 + 8];
            al[mt][0] = sAl[st][t][r0];
            al[mt][1] = sAl[st][t][r0 + 8];
            al[mt][2] = sAl[st][t + 4][r0];
            al[mt][3] = sAl[st][t + 4][r0 + 8];
        }
#pragma unroll
        for (int nt = 0; nt < NT; nt++) {
            int n0 = wn + nt * 8 + g;
            bh[nt][0] = sBh[st][t][n0];
            bh[nt][1] = sBh[st][t + 4][n0];
            bl[nt][0] = sBl[st][t][n0];
            bl[nt][1] = sBl[st][t + 4][n0];
        }
#pragma unroll
        for (int mt = 0; mt < MT; mt++)
#pragma unroll
            for (int nt = 0; nt < NT; nt++) {
                mma16bf(acc[mt][nt], ah[mt], bh[nt]);
                mma16bf(acc[mt][nt], ah[mt], bl[nt]);
                mma16bf(acc[mt][nt], al[mt], bh[nt]);
            }

        if (more) storeS(st ^ 1);
        __syncthreads();
        st ^= 1;
    }

#pragma unroll
    for (int mt = 0; mt < MT; mt++) {
        int r0 = blockRow + wm + mt * 16 + g;
#pragma unroll
        for (int nt = 0; nt < NT; nt++) {
            int c0 = blockCol + wn + nt * 8 + 2 * t;
            *(float2*)(Cout + (size_t)r0 * Ndim + c0) =
                make_float2(acc[mt][nt][0], acc[mt][nt][1]);
            *(float2*)(Cout + (size_t)(r0 + 8) * Ndim + c0) =
                make_float2(acc[mt][nt][2], acc[mt][nt][3]);
        }
    }
}

// ---------------------------------------------------------------------------
// fp16 single-product main GEMM. A = g_Ph (pre-packed fp16 pairs along k),
// B = M fp32 rounded once at smem-store. Epilogue: relu(acc/deg + bias).
// ---------------------------------------------------------------------------
template <int BM, int BN, int WGM, int WGN>
__global__ __launch_bounds__(256, 1)
void gemm_fp16_main(const uint32_t* __restrict__ Ah, const float* __restrict__ B,
                    float* __restrict__ C, int Mdim, int Ndim, int Kfull,
                    const float* __restrict__ bias, const float* __restrict__ deg) {
    constexpr int WM = BM / WGM, WN = BN / WGN;
    constexpr int MT = WM / 16, NT = WN / 8;
    constexpr int SA = BM + 8, SB = BN + 8;
    constexpr int LA = BM / 64;

    __shared__ uint32_t sAh[2][8][SA];
    __shared__ uint32_t sBh[2][8][SB];

    const int tid = threadIdx.x, wid = tid >> 5, lane = tid & 31;
    const int g = lane >> 2, t = lane & 3;
    const int wm = (wid / WGN) * WM, wn = (wid % WGN) * WN;
    const int blockRow = blockIdx.y * BM, blockCol = blockIdx.x * BN;

    float acc[MT][NT][4];
#pragma unroll
    for (int i = 0; i < MT; i++)
#pragma unroll
        for (int j = 0; j < NT; j++)
#pragma unroll
            for (int k = 0; k < 4; k++) acc[i][j][k] = 0.f;

    const int Kp = Kfull >> 1;                 // uint32 pairs per A row (256)
    const uint32_t* Aptr = Ah + (size_t)blockRow * Kp;
    const float* Bptr = B + blockCol;

    int ar[LA], aq[LA];
#pragma unroll
    for (int i = 0; i < LA; i++) { int id = tid + i * 256; ar[i] = id >> 2; aq[i] = id & 3; }
    const int bk2 = tid / (BN / 4), bn4 = tid % (BN / 4);

    uint2 raA[LA];
    float4 rbB0, rbB1;

    auto loadG = [&](int kt) {
        const int k0 = kt << 4, kp0 = kt << 3;
#pragma unroll
        for (int i = 0; i < LA; i++)
            raA[i] = *(const uint2*)(Aptr + (size_t)ar[i] * Kp + kp0 + aq[i] * 2);
        rbB0 = *(const float4*)(Bptr + (size_t)(k0 + 2 * bk2) * Ndim + bn4 * 4);
        rbB1 = *(const float4*)(Bptr + (size_t)(k0 + 2 * bk2 + 1) * Ndim + bn4 * 4);
    };

    auto storeS = [&](int st) {
#pragma unroll
        for (int i = 0; i < LA; i++) {
            sAh[st][aq[i] * 2 + 0][ar[i]] = raA[i].x;
            sAh[st][aq[i] * 2 + 1][ar[i]] = raA[i].y;
        }
        {
            float b0[4] = {rbB0.x, rbB0.y, rbB0.z, rbB0.w};
            float b1[4] = {rbB1.x, rbB1.y, rbB1.z, rbB1.w};
#pragma unroll
            for (int j = 0; j < 4; j++)
                sBh[st][bk2][bn4 * 4 + j] = pack_h2(b0[j], b1[j]);
        }
    };

    const int nK = Kfull >> 4;
    loadG(0);
    storeS(0);
    __syncthreads();

    int st = 0;
    for (int kt = 0; kt < nK; kt++) {
        const bool more = (kt + 1 < nK);
        if (more) loadG(kt + 1);

        uint32_t ah[MT][4], bh[NT][2];
#pragma unroll
        for (int mt = 0; mt < MT; mt++) {
            int r0 = wm + mt * 16 + g;
            ah[mt][0] = sAh[st][t][r0];
            ah[mt][1] = sAh[st][t][r0 + 8];
            ah[mt][2] = sAh[st][t + 4][r0];
            ah[mt][3] = sAh[st][t + 4][r0 + 8];
        }
#pragma unroll
        for (int nt = 0; nt < NT; nt++) {
            int n0 = wn + nt * 8 + g;
            bh[nt][0] = sBh[st][t][n0];
            bh[nt][1] = sBh[st][t + 4][n0];
        }
#pragma unroll
        for (int mt = 0; mt < MT; mt++)
#pragma unroll
            for (int nt = 0; nt < NT; nt++)
                mma16h(acc[mt][nt], ah[mt], bh[nt]);

        if (more) storeS(st ^ 1);
        __syncthreads();
        st ^= 1;
    }

#pragma unroll
    for (int mt = 0; mt < MT; mt++) {
        int r0 = blockRow + wm + mt * 16 + g;
        float inv0 = 1.0f / deg[r0];
        float inv1 = 1.0f / deg[r0 + 8];
#pragma unroll
        for (int nt = 0; nt < NT; nt++) {
            int c0 = blockCol + wn + nt * 8 + 2 * t;
            float b0 = bias[c0], b1 = bias[c0 + 1];
            float v00 = fmaxf(acc[mt][nt][0] * inv0 + b0, 0.f);
            float v01 = fmaxf(acc[mt][nt][1] * inv0 + b1, 0.f);
            float v10 = fmaxf(acc[mt][nt][2] * inv1 + b0, 0.f);
            float v11 = fmaxf(acc[mt][nt][3] * inv1 + b1, 0.f);
            *(float2*)(C + (size_t)r0 * Ndim + c0)       = make_float2(v00, v01);
            *(float2*)(C + (size_t)(r0 + 8) * Ndim + c0) = make_float2(v10, v11);
        }
    }
}

// ---------------------------------------------------------------------------
// launch: R14 fork-join schedule; nodes2h precedes agg on origin.
// ---------------------------------------------------------------------------
extern "C" void kernel_launch(void* const* d_in, const int* in_sizes, int n_in,
                              void* d_out, int out_size) {
    const float* nodes = (const float*)d_in[0];
    const float* adj   = (const float*)d_in[1];
    const float* W     = (const float*)d_in[2];
    const float* b     = (const float*)d_in[3];
    const float* K     = (const float*)d_in[4];
    // A_self/A_neigh/num_heads mathematically unused (softmax of row-constant
    // score + adjacency mask == adj/deg exactly, given guaranteed self-loops).

    const int D = in_sizes[3];               // 512
    const int N = in_sizes[0] / D;           // 4096
    const int H = in_sizes[4] / (D * D);     // 4
    float* out = (float*)d_out;

    float *pKbar, *pM, *pMpart, *pc, *pdeg;
    uint32_t* pPh;
    cudaGetSymbolAddress((void**)&pKbar,  g_Kbar);
    cudaGetSymbolAddress((void**)&pM,     g_M);
    cudaGetSymbolAddress((void**)&pMpart, g_Mpart);
    cudaGetSymbolAddress((void**)&pc,     g_c);
    cudaGetSymbolAddress((void**)&pPh,    g_Ph);
    cudaGetSymbolAddress((void**)&pdeg,   g_deg);

    const int DD4 = D * D / 4;
    const int total2 = N * D / 2;

    static cudaStream_t s2 = nullptr;
    static cudaEvent_t eFork = nullptr, eJoin = nullptr;
    if (s2 == nullptr) {
        cudaStreamCreateWithFlags(&s2, cudaStreamNonBlocking);
        cudaEventCreateWithFlags(&eFork, cudaEventDisableTiming);
        cudaEventCreateWithFlags(&eJoin, cudaEventDisableTiming);
    }

    // fork
    cudaEventRecord(eFork, 0);
    cudaStreamWaitEvent(s2, eFork, 0);

    // --- side stream: M-path ---
    kbar_kernel<<<(DD4 + 255) / 256, 256, 0, s2>>>(K, H, DD4);
    cvec_part<<<8, 256, 0, s2>>>(b, D);
    {
        dim3 grid(D / 64, D / 64, 4);
        gemm_bf16<64, 64, 2, 4><<<grid, 256, 0, s2>>>(W, pKbar, pMpart, D, D, D);
    }
    reduce_kernel<<<DD4 / 256 + 1, 256, 0, s2>>>(DD4, D);
    cudaEventRecord(eJoin, s2);

    // --- origin stream: nodes->fp16, then sparse aggregation ---
    nodes2h_kernel<<<(total2 + 255) / 256, 256>>>(nodes, total2);
    agg2_kernel<<<N / 2, 256>>>(adj, N, D);

    // join, then main GEMM
    cudaStreamWaitEvent(0, eJoin, 0);
    {
        dim3 grid(D / 128, N / 128, 1);
        gemm_fp16_main<128, 128, 4, 2><<<grid, 256>>>(pPh, pM, out,
                                                      N, D, D, pc, pdeg);
    }
    (void)n_in; (void)out_size;
}